// round 11
// baseline (speedup 1.0000x reference)
#include <cuda_runtime.h>
#include <cuda_bf16.h>

// Causal BoW = running mean along T. Shapes: B=32, T=2048, C=512, fp32.
//
// Single-pass CHAINED scan, PERSISTENT + SOFTWARE-PIPELINED, BARRIER-FREE:
//  tile = (chain, tk): chain = (b, c-quarter) -> 128 chains; tk = chunk of
//  R=32 rows -> 64 chunks/chain; 8192 tiles.
//  Grid = 512 CTAs x 128 threads, 4 CTAs/SM guaranteed resident
//  (launch_bounds(128,4): 512 < 4*148). CTA k statically owns tiles
//  k, k+512, ..., k+15*512 (tk-interleaved). All 512 CTAs are wave-1
//  resident => static in-order processing is deadlock-free (tile i waits
//  only on tile i-128, owned by a resident CTA processing smaller tiles).
//  DOUBLE BUFFERING: while tile j is scanned/spun/stored, tile j+1's 32
//  loads are already in flight. The protocol is entirely per-thread
//  (packed u64 publish via atomicExch, volatile spin + consume-reset), so
//  the kernel has ZERO barriers and zero shared memory: warps flow
//  independently. 1/(t+1) via __fdividef (2 ulp << 1e-3 tolerance).
//  Self-cleaning: every published slot is consumed-and-reset by its unique
//  successor; last tk level never publishes. No ticket, no counters =>
//  all device state returns to zero after every launch. Graph-safe.

#define B_DIM 32
#define T_DIM 2048
#define C_DIM 512
#define R_ROWS 32
#define CGROUP 128
#define NCHAINS 128                  // B_DIM * (C_DIM / CGROUP)
#define NTK (T_DIM / R_ROWS)         // 64
#define NTILES (NCHAINS * NTK)       // 8192
#define GRID 512
#define TPC (NTILES / GRID)          // 16 tiles per CTA

__device__ unsigned long long g_incl[(size_t)NTILES * CGROUP];  // 8 MB packed

__device__ __forceinline__ size_t tile_base(unsigned vt, unsigned tid) {
    const unsigned chain = vt & (NCHAINS - 1);
    const unsigned tk = vt >> 7;                 // vt / NCHAINS
    const unsigned b  = chain >> 2;
    const unsigned cq = chain & 3;
    const unsigned c  = cq * CGROUP + tid;
    return (size_t)b * (T_DIM * C_DIM) + (size_t)(tk * R_ROWS) * C_DIM + c;
}

__device__ __forceinline__ void load_tile(float (&v)[R_ROWS],
                                          const float* __restrict__ xp) {
    #pragma unroll
    for (int u = 0; u < R_ROWS; ++u)
        v[u] = __ldg(xp + (size_t)u * C_DIM);
}

__device__ __forceinline__ void process_tile(float (&v)[R_ROWS], unsigned vt,
                                             float* __restrict__ op,
                                             unsigned tid) {
    // Local inclusive scan in registers.
    #pragma unroll
    for (int u = 1; u < R_ROWS; ++u)
        v[u] += v[u - 1];

    // Resolve prefix: per-thread spin on predecessor's packed word, then
    // consume-and-reset so the slot is zero for the next launch.
    float prefix = 0.0f;
    if (vt >= NCHAINS) {
        unsigned long long* predp =
            &g_incl[(size_t)(vt - NCHAINS) * CGROUP + tid];
        unsigned long long pk;
        do { pk = *(volatile unsigned long long*)predp; }
        while ((pk >> 32) == 0ull);
        prefix = __uint_as_float((unsigned)(pk & 0xFFFFFFFFu));
        *(volatile unsigned long long*)predp = 0ull;   // consume-reset
    }

    // Publish inclusive prefix — except the last tk level (no successor).
    // Published BEFORE the output stores so successors unblock early.
    if (vt < NTILES - NCHAINS) {
        const unsigned long long pk = (1ull << 32)
            | (unsigned long long)__float_as_uint(prefix + v[R_ROWS - 1]);
        atomicExch(&g_incl[(size_t)vt * CGROUP + tid], pk);
    }

    // Scaled output: (prefix + incl) / (t+1). Streaming stores.
    const int t0 = (int)(vt >> 7) * R_ROWS;
    #pragma unroll
    for (int u = 0; u < R_ROWS; ++u) {
        const float inv = __fdividef(1.0f, (float)(t0 + u + 1));
        __stcs(op + (size_t)u * C_DIM, (prefix + v[u]) * inv);
    }
}

__global__ void __launch_bounds__(CGROUP, 4)
causal_bow_scan(const float* __restrict__ x, float* __restrict__ out) {
    const unsigned tid = threadIdx.x;
    const unsigned bid = blockIdx.x;

    float vA[R_ROWS], vB[R_ROWS];

    // Prologue: issue loads for tile j=0.
    load_tile(vA, x + tile_base(bid, tid));

    #pragma unroll 1
    for (int j = 0; j < TPC; j += 2) {
        const unsigned vtA = bid + (unsigned)j * GRID;
        const unsigned vtB = vtA + GRID;

        // Prefetch tile j+1 while tile j is processed.
        load_tile(vB, x + tile_base(vtB, tid));
        process_tile(vA, vtA, out + tile_base(vtA, tid), tid);

        // Prefetch tile j+2 while tile j+1 is processed.
        if (j + 2 < TPC)
            load_tile(vA, x + tile_base(vtA + 2u * GRID, tid));
        process_tile(vB, vtB, out + tile_base(vtB, tid), tid);
    }
}

extern "C" void kernel_launch(void* const* d_in, const int* in_sizes, int n_in,
                              void* d_out, int out_size) {
    const float* x = (const float*)d_in[0];
    float* out = (float*)d_out;
    (void)in_sizes; (void)n_in; (void)out_size;

    causal_bow_scan<<<GRID, CGROUP>>>(x, out);
}

// round 12
// speedup vs baseline: 1.5264x; 1.5264x over previous
#include <cuda_runtime.h>
#include <cuda_bf16.h>

// Causal BoW = running mean along T. Shapes: B=32, T=2048, C=512, fp32.
//
// Single-pass CHAINED scan (StreamScan-style), BARRIER-FREE, SELF-CLEANING:
//  tile = blockIdx.x = (tk, chain): chain = (b, c-quarter) -> 128 chains;
//  tk = chunk of R=64 rows -> 32 chunks/chain; 4096 tiles.
//  128-thread CTA = one thread per column, 64 rows in registers, 6 CTAs/SM.
//  NO ticket, NO barriers, NO shared memory: the publish/consume protocol
//  is entirely per-thread, so warps flow independently (a warp can store
//  while a sibling warp still spins). Tile i spins only on tile i-128;
//  blocks dispatch in increasing blockIdx order, so the predecessor's CTA
//  is always dispatched first and never waits on a later tile -> progress
//  by induction (classic StreamScan assumption).
//  Per-column inclusive prefixes published as ONE packed 64-bit word
//  (status<<32 | float bits) via atomicExch, BEFORE the output stores so
//  successors unblock early. Successor threads spin with volatile 64-bit
//  loads, then RESET the slot (consume-and-reset). Last tk level never
//  publishes. => all device state returns to zero after every launch:
//  deterministic, graph-safe, no aux kernels, no allocations.
//  1/(t+1) via __fdividef (<=2 ulp, tolerance is 1e-3).

#define B_DIM 32
#define T_DIM 2048
#define C_DIM 512
#define R_ROWS 64
#define CGROUP 128
#define NCHAINS 128                      // B_DIM * (C_DIM / CGROUP)
#define NTK (T_DIM / R_ROWS)             // 32
#define NTILES (NCHAINS * NTK)           // 4096

__device__ unsigned long long g_incl[(size_t)NTILES * CGROUP];  // 4 MB packed

__global__ void __launch_bounds__(CGROUP, 6)
causal_bow_scan(const float* __restrict__ x, float* __restrict__ out) {
    const unsigned tid = threadIdx.x;
    const unsigned vt  = blockIdx.x;            // tile id = dispatch order

    const unsigned chain = vt & (NCHAINS - 1);
    const unsigned tk    = vt >> 7;             // vt / NCHAINS
    const unsigned b  = chain >> 2;
    const unsigned cq = chain & 3;
    const unsigned c  = cq * CGROUP + tid;
    const int t0 = (int)tk * R_ROWS;

    const size_t base = (size_t)b * (T_DIM * C_DIM)
                      + (size_t)t0 * C_DIM + c;
    const float* __restrict__ xp = x + base;
    float* __restrict__ op = out + base;

    // Batched independent loads: 64 coalesced 128B lines in flight per warp.
    float v[R_ROWS];
    #pragma unroll
    for (int u = 0; u < R_ROWS; ++u)
        v[u] = __ldg(xp + (size_t)u * C_DIM);

    // Local inclusive scan in registers.
    #pragma unroll
    for (int u = 1; u < R_ROWS; ++u)
        v[u] += v[u - 1];

    // Resolve prefix: per-thread spin on predecessor's packed word, then
    // consume-and-reset so the slot is zero for the next launch.
    float prefix = 0.0f;
    if (vt >= NCHAINS) {
        unsigned long long* predp =
            &g_incl[(size_t)(vt - NCHAINS) * CGROUP + tid];
        unsigned long long pk;
        do { pk = *(volatile unsigned long long*)predp; }
        while ((pk >> 32) == 0ull);
        prefix = __uint_as_float((unsigned)(pk & 0xFFFFFFFFu));
        *(volatile unsigned long long*)predp = 0ull;   // consume-reset
    }

    // Publish inclusive prefix — except the last tk level (no successor).
    // Published BEFORE the 64 output stores so successors unblock early.
    if (vt < NTILES - NCHAINS) {
        const unsigned long long pk = (1ull << 32)
            | (unsigned long long)__float_as_uint(prefix + v[R_ROWS - 1]);
        atomicExch(&g_incl[(size_t)vt * CGROUP + tid], pk);
    }

    // Scaled output: (prefix + incl) / (t+1). Streaming stores.
    #pragma unroll
    for (int u = 0; u < R_ROWS; ++u) {
        const float inv = __fdividef(1.0f, (float)(t0 + u + 1));
        __stcs(op + (size_t)u * C_DIM, (prefix + v[u]) * inv);
    }
}

extern "C" void kernel_launch(void* const* d_in, const int* in_sizes, int n_in,
                              void* d_out, int out_size) {
    const float* x = (const float*)d_in[0];
    float* out = (float*)d_out;
    (void)in_sizes; (void)n_in; (void)out_size;

    causal_bow_scan<<<NTILES, CGROUP>>>(x, out);
}